// round 5
// baseline (speedup 1.0000x reference)
#include <cuda_runtime.h>
#include <math.h>
#include <stdint.h>

#define SEQ  2048
#define BAT  2
#define DM   1024
#define NH   16
#define HDM  64
#define DFF  4096
#define ROWS (SEQ*BAT)   // 4096

// ---------------- scratch (static device globals; no allocation) ----------------
__device__ float g_xln[ROWS * DM];
__device__ float g_qkv[ROWS * 3 * DM];
__device__ float g_q[BAT * NH * SEQ * HDM];
__device__ float g_k[BAT * NH * SEQ * HDM];
__device__ float g_v[BAT * NH * SEQ * HDM];
__device__ float g_att[ROWS * DM];
__device__ float g_x[ROWS * DM];
__device__ float g_h1[ROWS * DFF];
// tf32-rounded weights
__device__ float g_wqkv[3 * DM * DM];
__device__ float g_wo[DM * DM];
__device__ float g_w1[DFF * DM];
__device__ float g_w2[DM * DFF];

__device__ __forceinline__ uint32_t f2tf32(float f) {
    uint32_t u;
    asm("cvt.rna.tf32.f32 %0, %1;" : "=r"(u) : "f"(f));
    return u;
}
__device__ __forceinline__ float rtf(float f) { return __uint_as_float(f2tf32(f)); }

// ---------------- weight pre-round ----------------
__global__ __launch_bounds__(256) void round_kernel(
    const float* __restrict__ in, float* __restrict__ out, int n4)
{
    int i = blockIdx.x * 256 + threadIdx.x;
    if (i < n4) {
        float4 v = ((const float4*)in)[i];
        v.x = rtf(v.x); v.y = rtf(v.y); v.z = rtf(v.z); v.w = rtf(v.w);
        ((float4*)out)[i] = v;
    }
}

// ---------------- LayerNorm (tf32-rounded output; feeds only GEMM A) ----------------
__global__ __launch_bounds__(256) void ln_kernel(
    const float* __restrict__ x, const float* __restrict__ g,
    const float* __restrict__ b, float* __restrict__ y)
{
    int row = blockIdx.x;
    int t = threadIdx.x;
    const float4* xr = (const float4*)(x + (size_t)row * DM);
    float4 v = xr[t];
    float s  = v.x + v.y + v.z + v.w;
    float ss = v.x*v.x + v.y*v.y + v.z*v.z + v.w*v.w;
    #pragma unroll
    for (int o = 16; o > 0; o >>= 1) {
        s  += __shfl_xor_sync(0xffffffffu, s,  o);
        ss += __shfl_xor_sync(0xffffffffu, ss, o);
    }
    __shared__ float red[18];
    if ((t & 31) == 0) { red[t >> 5] = s; red[(t >> 5) + 8] = ss; }
    __syncthreads();
    if (t == 0) {
        float S_ = 0.f, SS = 0.f;
        #pragma unroll
        for (int i = 0; i < 8; i++) { S_ += red[i]; SS += red[i + 8]; }
        float mu  = S_ * (1.f / DM);
        float var = SS * (1.f / DM) - mu * mu;
        red[16] = mu;
        red[17] = rsqrtf(var + 1e-5f);
    }
    __syncthreads();
    float mu = red[16], inv = red[17];
    float4 gg = ((const float4*)g)[t];
    float4 bb = ((const float4*)b)[t];
    float4 o;
    o.x = rtf((v.x - mu) * inv * gg.x + bb.x);
    o.y = rtf((v.y - mu) * inv * gg.y + bb.y);
    o.z = rtf((v.z - mu) * inv * gg.z + bb.z);
    o.w = rtf((v.w - mu) * inv * gg.w + bb.w);
    ((float4*)(y + (size_t)row * DM))[t] = o;
}

// ---------------- tf32 TC GEMM v2: 128x256 block, 8 warps of 64x64, 3-stage ----------------
// Inputs A and W must already be tf32-rounded. C[M,N] = A[M,K] @ W[N,K]^T.
#define CPA16(dst, src) \
    asm volatile("cp.async.cg.shared.global [%0], [%1], 16;\n" :: "r"(dst), "l"(src))

#define GLDS 20
#define GSTAGE (384 * GLDS)           // floats per stage (A 128 rows + B 256 rows)
#define GSMEM_BYTES (3 * GSTAGE * 4)  // 92160

template<bool RELU, bool RES, bool ROUND>
__global__ __launch_bounds__(256) void gemm_tc2(
    const float* __restrict__ A, const float* __restrict__ W,
    const float* __restrict__ bias, const float* __restrict__ res,
    float* __restrict__ C, int M, int N, int K)
{
    extern __shared__ float sh[];
    int tid = threadIdx.x;
    int warp = tid >> 5, lane = tid & 31;
    int wm = warp >> 2, wn = warp & 3;          // 2 x 4 warps
    int grp = lane >> 2, tig = lane & 3;
    int m0 = blockIdx.y << 7, n0 = blockIdx.x << 8;

    // loaders: A 128x16 (2 float4/thread), B 256x16 (4 float4/thread)
    int arow = tid >> 1, acol = (tid & 1) << 3;
    const float* Ag = A + (size_t)(m0 + arow) * K + acol;
    const float* Bg = W + (size_t)(n0 + tid) * K;
    uint32_t shbase = (uint32_t)__cvta_generic_to_shared(sh);
    uint32_t aoff = (uint32_t)(arow * GLDS + acol) * 4u;
    uint32_t boff = (uint32_t)(128 * GLDS + tid * GLDS) * 4u;

    float acc[4][8][4];
    #pragma unroll
    for (int mt = 0; mt < 4; mt++)
        #pragma unroll
        for (int nt = 0; nt < 8; nt++)
            #pragma unroll
            for (int i = 0; i < 4; i++) acc[mt][nt][i] = 0.f;

    int KT = K >> 4;

    // prologue: stages 0,1
    #pragma unroll
    for (int s = 0; s < 2; s++) {
        uint32_t base = shbase + s * (GSTAGE * 4);
        int k0 = s << 4;
        CPA16(base + aoff, Ag + k0);
        CPA16(base + aoff + 16, Ag + k0 + 4);
        uint32_t bb = base + boff;
        CPA16(bb,      Bg + k0);
        CPA16(bb + 16, Bg + k0 + 4);
        CPA16(bb + 32, Bg + k0 + 8);
        CPA16(bb + 48, Bg + k0 + 12);
        asm volatile("cp.async.commit_group;\n");
    }

    int s_comp = 0, s_load = 2;
    for (int kt = 0; kt < KT; kt++) {
        if (kt + 1 < KT) asm volatile("cp.async.wait_group 1;\n");
        else             asm volatile("cp.async.wait_group 0;\n");
        __syncthreads();
        if (kt + 2 < KT) {
            uint32_t base = shbase + s_load * (GSTAGE * 4);
            int k0 = (kt + 2) << 4;
            CPA16(base + aoff, Ag + k0);
            CPA16(base + aoff + 16, Ag + k0 + 4);
            uint32_t bb = base + boff;
            CPA16(bb,      Bg + k0);
            CPA16(bb + 16, Bg + k0 + 4);
            CPA16(bb + 32, Bg + k0 + 8);
            CPA16(bb + 48, Bg + k0 + 12);
            asm volatile("cp.async.commit_group;\n");
        }
        if (++s_load == 3) s_load = 0;

        const float* As = sh + s_comp * GSTAGE;
        const float* Bs = As + 128 * GLDS;
        if (++s_comp == 3) s_comp = 0;

        #pragma unroll
        for (int kk = 0; kk < 16; kk += 8) {
            uint32_t a[4][4];
            #pragma unroll
            for (int mt = 0; mt < 4; mt++) {
                int rb = wm * 64 + mt * 16;
                a[mt][0] = __float_as_uint(As[(rb + grp)     * GLDS + kk + tig]);
                a[mt][1] = __float_as_uint(As[(rb + grp + 8) * GLDS + kk + tig]);
                a[mt][2] = __float_as_uint(As[(rb + grp)     * GLDS + kk + tig + 4]);
                a[mt][3] = __float_as_uint(As[(rb + grp + 8) * GLDS + kk + tig + 4]);
            }
            #pragma unroll
            for (int nt = 0; nt < 8; nt++) {
                int cb = wn * 64 + nt * 8;
                uint32_t b0 = __float_as_uint(Bs[(cb + grp) * GLDS + kk + tig]);
                uint32_t b1 = __float_as_uint(Bs[(cb + grp) * GLDS + kk + tig + 4]);
                #pragma unroll
                for (int mt = 0; mt < 4; mt++) {
                    asm volatile(
                        "mma.sync.aligned.m16n8k8.row.col.f32.tf32.tf32.f32 "
                        "{%0,%1,%2,%3}, {%4,%5,%6,%7}, {%8,%9}, {%0,%1,%2,%3};\n"
                        : "+f"(acc[mt][nt][0]), "+f"(acc[mt][nt][1]),
                          "+f"(acc[mt][nt][2]), "+f"(acc[mt][nt][3])
                        : "r"(a[mt][0]), "r"(a[mt][1]), "r"(a[mt][2]), "r"(a[mt][3]),
                          "r"(b0), "r"(b1));
                }
            }
        }
    }

    #pragma unroll
    for (int mt = 0; mt < 4; mt++) {
        int r = m0 + wm * 64 + mt * 16 + grp;
        #pragma unroll
        for (int nt = 0; nt < 8; nt++) {
            int c = n0 + wn * 64 + nt * 8 + tig * 2;
            float2 bv = *(const float2*)(bias + c);
            #pragma unroll
            for (int half = 0; half < 2; half++) {
                int rr = r + half * 8;
                float2 o;
                o.x = acc[mt][nt][half * 2 + 0] + bv.x;
                o.y = acc[mt][nt][half * 2 + 1] + bv.y;
                if (RES) {
                    float2 rv = *(const float2*)(res + (size_t)rr * N + c);
                    o.x += rv.x; o.y += rv.y;
                }
                if (RELU) { o.x = fmaxf(o.x, 0.f); o.y = fmaxf(o.y, 0.f); }
                if (ROUND) { o.x = rtf(o.x); o.y = rtf(o.y); }
                *(float2*)(C + (size_t)rr * N + c) = o;
            }
        }
    }
}

// ---------------- RoPE: outputs tf32-rounded, Q pre-scaled by 1/8 ----------------
__global__ __launch_bounds__(256) void rope_kernel(
    const float* __restrict__ qkv, const float* __restrict__ sn,
    const float* __restrict__ cs,
    float* __restrict__ Q, float* __restrict__ K, float* __restrict__ V)
{
    int idx = blockIdx.x * 256 + threadIdx.x;
    int p = idx & 31;
    int s = (idx >> 5) & 2047;
    int h = (idx >> 16) & 15;
    int b = idx >> 20;
    size_t rb = ((size_t)s * BAT + b) * (3 * DM) + h * HDM + 2 * p;
    float2 q = *(const float2*)(qkv + rb);
    float2 k = *(const float2*)(qkv + rb + DM);
    float2 v = *(const float2*)(qkv + rb + 2 * DM);
    float sv = sn[s * 32 + p], cv = cs[s * 32 + p];
    float2 qo = make_float2(rtf((q.x * cv - q.y * sv) * 0.125f),
                            rtf((q.y * cv + q.x * sv) * 0.125f));
    float2 ko = make_float2(rtf(k.x * cv - k.y * sv), rtf(k.y * cv + k.x * sv));
    float2 vo = make_float2(rtf(v.x), rtf(v.y));
    size_t ob = ((size_t)(b * NH + h) * SEQ + s) * HDM + 2 * p;
    *(float2*)(Q + ob) = qo;
    *(float2*)(K + ob) = ko;
    *(float2*)(V + ob) = vo;
}

// ---------------- tf32 TC flash attention (inputs pre-rounded) ----------------
#define KS_LD 68
#define VS_LD 72

__global__ __launch_bounds__(128) void attn_tc(
    const float* __restrict__ Q, const float* __restrict__ K,
    const float* __restrict__ V, float* __restrict__ Out)
{
    extern __shared__ float sm[];
    float* Ks = sm;                     // 64 x 68
    float* Vs = sm + 64 * KS_LD;        // 64 x 72
    float* Ps = Vs + 64 * VS_LD;        // 64 x 68 (Q staging, then P)
    int tid = threadIdx.x;
    int warp = tid >> 5, lane = tid & 31;
    int grp = lane >> 2, tig = lane & 3;
    int qb = blockIdx.x, bh = blockIdx.y;
    int b = bh >> 4, h = bh & 15;
    int rb = warp * 16;

    const float* Qg = Q + ((size_t)bh * SEQ + qb * 64) * HDM;
    #pragma unroll
    for (int i = 0; i < 8; i++) {
        int idx = tid + i * 128;
        int r = idx >> 4, c = (idx & 15) << 2;
        float4 v = *(const float4*)(Qg + r * 64 + c);
        Ps[r * KS_LD + c + 0] = v.x;
        Ps[r * KS_LD + c + 1] = v.y;
        Ps[r * KS_LD + c + 2] = v.z;
        Ps[r * KS_LD + c + 3] = v.w;
    }
    __syncthreads();

    uint32_t qa[8][4];
    #pragma unroll
    for (int kk = 0; kk < 8; kk++) {
        qa[kk][0] = __float_as_uint(Ps[(rb + grp)     * KS_LD + kk * 8 + tig]);
        qa[kk][1] = __float_as_uint(Ps[(rb + grp + 8) * KS_LD + kk * 8 + tig]);
        qa[kk][2] = __float_as_uint(Ps[(rb + grp)     * KS_LD + kk * 8 + tig + 4]);
        qa[kk][3] = __float_as_uint(Ps[(rb + grp + 8) * KS_LD + kk * 8 + tig + 4]);
    }

    float oacc[8][4];
    #pragma unroll
    for (int nt = 0; nt < 8; nt++)
        #pragma unroll
        for (int i = 0; i < 4; i++) oacc[nt][i] = 0.f;
    float m_i[2] = {-1e30f, -1e30f};
    float l_i[2] = {0.f, 0.f};

    for (int kb = 0; kb <= qb; kb++) {
        __syncthreads();
        const float* Kg = K + ((size_t)bh * SEQ + kb * 64) * HDM;
        const float* Vg = V + ((size_t)bh * SEQ + kb * 64) * HDM;
        #pragma unroll
        for (int i = 0; i < 8; i++) {
            int idx = tid + i * 128;
            int r = idx >> 4, c = (idx & 15) << 2;
            float4 kv = *(const float4*)(Kg + r * 64 + c);
            Ks[r * KS_LD + c + 0] = kv.x;
            Ks[r * KS_LD + c + 1] = kv.y;
            Ks[r * KS_LD + c + 2] = kv.z;
            Ks[r * KS_LD + c + 3] = kv.w;
            float4 vv = *(const float4*)(Vg + r * 64 + c);
            Vs[r * VS_LD + c + 0] = vv.x;
            Vs[r * VS_LD + c + 1] = vv.y;
            Vs[r * VS_LD + c + 2] = vv.z;
            Vs[r * VS_LD + c + 3] = vv.w;
        }
        __syncthreads();

        float sacc[8][4];
        #pragma unroll
        for (int nt = 0; nt < 8; nt++)
            #pragma unroll
            for (int i = 0; i < 4; i++) sacc[nt][i] = 0.f;
        #pragma unroll
        for (int kk = 0; kk < 8; kk++) {
            #pragma unroll
            for (int nt = 0; nt < 8; nt++) {
                uint32_t b0 = __float_as_uint(Ks[(nt * 8 + grp) * KS_LD + kk * 8 + tig]);
                uint32_t b1 = __float_as_uint(Ks[(nt * 8 + grp) * KS_LD + kk * 8 + tig + 4]);
                asm volatile(
                    "mma.sync.aligned.m16n8k8.row.col.f32.tf32.tf32.f32 "
                    "{%0,%1,%2,%3}, {%4,%5,%6,%7}, {%8,%9}, {%0,%1,%2,%3};\n"
                    : "+f"(sacc[nt][0]), "+f"(sacc[nt][1]),
                      "+f"(sacc[nt][2]), "+f"(sacc[nt][3])
                    : "r"(qa[kk][0]), "r"(qa[kk][1]), "r"(qa[kk][2]), "r"(qa[kk][3]),
                      "r"(b0), "r"(b1));
            }
        }

        if (kb == qb) {
            #pragma unroll
            for (int nt = 0; nt < 8; nt++) {
                int c0 = nt * 8 + 2 * tig;
                int r0 = rb + grp;
                if (c0     > r0)     sacc[nt][0] = -1e30f;
                if (c0 + 1 > r0)     sacc[nt][1] = -1e30f;
                if (c0     > r0 + 8) sacc[nt][2] = -1e30f;
                if (c0 + 1 > r0 + 8) sacc[nt][3] = -1e30f;
            }
        }

        #pragma unroll
        for (int hf = 0; hf < 2; hf++) {
            float mx = -1e30f;
            #pragma unroll
            for (int nt = 0; nt < 8; nt++)
                mx = fmaxf(mx, fmaxf(sacc[nt][2 * hf], sacc[nt][2 * hf + 1]));
            mx = fmaxf(mx, __shfl_xor_sync(0xffffffffu, mx, 1));
            mx = fmaxf(mx, __shfl_xor_sync(0xffffffffu, mx, 2));
            float mn = fmaxf(m_i[hf], mx);
            float al = __expf(m_i[hf] - mn);
            float rs = 0.f;
            int prow = (rb + grp + 8 * hf) * KS_LD;
            #pragma unroll
            for (int nt = 0; nt < 8; nt++) {
                float p0 = __expf(sacc[nt][2 * hf]     - mn);
                float p1 = __expf(sacc[nt][2 * hf + 1] - mn);
                rs += p0 + p1;
                float2 st;
                st.x = __uint_as_float(f2tf32(p0));
                st.y = __uint_as_float(f2tf32(p1));
                *(float2*)(Ps + prow + nt * 8 + 2 * tig) = st;
                oacc[nt][2 * hf]     *= al;
                oacc[nt][2 * hf + 1] *= al;
            }
            rs += __shfl_xor_sync(0xffffffffu, rs, 1);
            rs += __shfl_xor_sync(0xffffffffu, rs, 2);
            l_i[hf] = l_i[hf] * al + rs;
            m_i[hf] = mn;
        }
        __syncwarp();

        #pragma unroll
        for (int kk = 0; kk < 8; kk++) {
            uint32_t a0 = __float_as_uint(Ps[(rb + grp)     * KS_LD + kk * 8 + tig]);
            uint32_t a1 = __float_as_uint(Ps[(rb + grp + 8) * KS_LD + kk * 8 + tig]);
            uint32_t a2 = __float_as_uint(Ps[(rb + grp)     * KS_LD + kk * 8 + tig + 4]);
            uint32_t a3 = __float_as_uint(Ps[(rb + grp + 8) * KS_LD + kk * 8 + tig + 4]);
            #pragma unroll
            for (int nt = 0; nt < 8; nt++) {
                uint32_t b0 = __float_as_uint(Vs[(kk * 8 + tig)     * VS_LD + nt * 8 + grp]);
                uint32_t b1 = __float_as_uint(Vs[(kk * 8 + tig + 4) * VS_LD + nt * 8 + grp]);
                asm volatile(
                    "mma.sync.aligned.m16n8k8.row.col.f32.tf32.tf32.f32 "
                    "{%0,%1,%2,%3}, {%4,%5,%6,%7}, {%8,%9}, {%0,%1,%2,%3};\n"
                    : "+f"(oacc[nt][0]), "+f"(oacc[nt][1]),
                      "+f"(oacc[nt][2]), "+f"(oacc[nt][3])
                    : "r"(a0), "r"(a1), "r"(a2), "r"(a3),
                      "r"(b0), "r"(b1));
            }
        }
    }

    float inv0 = 1.f / l_i[0], inv1 = 1.f / l_i[1];
    int q0 = qb * 64 + rb + grp;
    #pragma unroll
    for (int nt = 0; nt < 8; nt++) {
        int d = h * HDM + nt * 8 + 2 * tig;
        float2 o0 = make_float2(rtf(oacc[nt][0] * inv0), rtf(oacc[nt][1] * inv0));
        float2 o1 = make_float2(rtf(oacc[nt][2] * inv1), rtf(oacc[nt][3] * inv1));
        *(float2*)(Out + ((size_t)q0 * BAT + b) * DM + d)       = o0;
        *(float2*)(Out + ((size_t)(q0 + 8) * BAT + b) * DM + d) = o1;
    }
}

// ---------------- launcher ----------------
extern "C" void kernel_launch(void* const* d_in, const int* in_sizes, int n_in,
                              void* d_out, int out_size)
{
    const float* src  = (const float*)d_in[0];
    const float* sn   = (const float*)d_in[1];
    const float* cs   = (const float*)d_in[2];
    const float* wqkv = (const float*)d_in[3];
    const float* bqkv = (const float*)d_in[4];
    const float* wo   = (const float*)d_in[5];
    const float* bo   = (const float*)d_in[6];
    const float* g1   = (const float*)d_in[7];
    const float* be1  = (const float*)d_in[8];
    const float* g2   = (const float*)d_in[9];
    const float* be2  = (const float*)d_in[10];
    const float* w1   = (const float*)d_in[11];
    const float* bb1  = (const float*)d_in[12];
    const float* w2   = (const float*)d_in[13];
    const float* bb2  = (const float*)d_in[14];
    float* out = (float*)d_out;

    float *xln, *qkv, *q, *k, *v, *att, *x, *h1;
    float *rwqkv, *rwo, *rw1, *rw2;
    cudaGetSymbolAddress((void**)&xln, g_xln);
    cudaGetSymbolAddress((void**)&qkv, g_qkv);
    cudaGetSymbolAddress((void**)&q,   g_q);
    cudaGetSymbolAddress((void**)&k,   g_k);
    cudaGetSymbolAddress((void**)&v,   g_v);
    cudaGetSymbolAddress((void**)&att, g_att);
    cudaGetSymbolAddress((void**)&x,   g_x);
    cudaGetSymbolAddress((void**)&h1,  g_h1);
    cudaGetSymbolAddress((void**)&rwqkv, g_wqkv);
    cudaGetSymbolAddress((void**)&rwo,   g_wo);
    cudaGetSymbolAddress((void**)&rw1,   g_w1);
    cudaGetSymbolAddress((void**)&rw2,   g_w2);

    const int ATTN_SMEM = (64 * KS_LD + 64 * VS_LD + 64 * KS_LD) * 4;
    cudaFuncSetAttribute(attn_tc, cudaFuncAttributeMaxDynamicSharedMemorySize, ATTN_SMEM);
    cudaFuncSetAttribute(gemm_tc2<false, false, false>, cudaFuncAttributeMaxDynamicSharedMemorySize, GSMEM_BYTES);
    cudaFuncSetAttribute(gemm_tc2<false, true,  false>, cudaFuncAttributeMaxDynamicSharedMemorySize, GSMEM_BYTES);
    cudaFuncSetAttribute(gemm_tc2<true,  false, true >, cudaFuncAttributeMaxDynamicSharedMemorySize, GSMEM_BYTES);

    // 0. pre-round weights to tf32
    round_kernel<<<(3 * DM * DM / 4 + 255) / 256, 256>>>(wqkv, rwqkv, 3 * DM * DM / 4);
    round_kernel<<<(DM * DM / 4 + 255) / 256, 256>>>(wo, rwo, DM * DM / 4);
    round_kernel<<<(DFF * DM / 4 + 255) / 256, 256>>>(w1, rw1, DFF * DM / 4);
    round_kernel<<<(DM * DFF / 4 + 255) / 256, 256>>>(w2, rw2, DM * DFF / 4);

    // 1. LN1 (tf32 out)
    ln_kernel<<<ROWS, 256>>>(src, g1, be1, xln);
    // 2. QKV projection
    gemm_tc2<false, false, false><<<dim3(3 * DM / 256, ROWS / 128), 256, GSMEM_BYTES>>>(
        xln, rwqkv, bqkv, nullptr, qkv, ROWS, 3 * DM, DM);
    // 3. RoPE (tf32 out, Q pre-scaled)
    rope_kernel<<<(BAT * NH * SEQ * 32) / 256, 256>>>(qkv, sn, cs, q, k, v);
    // 4. attention (tf32 out)
    attn_tc<<<dim3(SEQ / 64, BAT * NH), 128, ATTN_SMEM>>>(q, k, v, att);
    // 5. out-proj + residual (fp32 out)
    gemm_tc2<false, true, false><<<dim3(DM / 256, ROWS / 128), 256, GSMEM_BYTES>>>(
        att, rwo, bo, src, x, ROWS, DM, DM);
    // 6. LN2 (tf32 out)
    ln_kernel<<<ROWS, 256>>>(x, g2, be2, xln);
    // 7. FFN up + ReLU (tf32 out)
    gemm_tc2<true, false, true><<<dim3(DFF / 256, ROWS / 128), 256, GSMEM_BYTES>>>(
        xln, rw1, bb1, nullptr, h1, ROWS, DFF, DM);
    // 8. FFN down + residual (fp32 out)
    gemm_tc2<false, true, false><<<dim3(DM / 256, ROWS / 128), 256, GSMEM_BYTES>>>(
        h1, rw2, bb2, x, out, ROWS, DM, DFF);
}

// round 7
// speedup vs baseline: 1.1890x; 1.1890x over previous
#include <cuda_runtime.h>
#include <math.h>
#include <stdint.h>

#define SEQ  2048
#define BAT  2
#define DM   1024
#define NH   16
#define HDM  64
#define DFF  4096
#define ROWS (SEQ*BAT)   // 4096

// ---------------- scratch (static device globals; no allocation) ----------------
__device__ float g_xln[ROWS * DM];
__device__ float g_qkv[ROWS * 3 * DM];
__device__ float g_q[BAT * NH * SEQ * HDM];
__device__ float g_k[BAT * NH * SEQ * HDM];
__device__ float g_v[BAT * NH * SEQ * HDM];
__device__ float g_att[ROWS * DM];
__device__ float g_x[ROWS * DM];
__device__ float g_h1[ROWS * DFF];
// tf32-rounded weights
__device__ float g_wqkv[3 * DM * DM];
__device__ float g_wo[DM * DM];
__device__ float g_w1[DFF * DM];
__device__ float g_w2[DM * DFF];

__device__ __forceinline__ uint32_t f2tf32(float f) {
    uint32_t u;
    asm("cvt.rna.tf32.f32 %0, %1;" : "=r"(u) : "f"(f));
    return u;
}
__device__ __forceinline__ float rtf(float f) { return __uint_as_float(f2tf32(f)); }

// ---------------- weight pre-round ----------------
__global__ __launch_bounds__(256) void round_kernel(
    const float* __restrict__ in, float* __restrict__ out, int n4)
{
    int i = blockIdx.x * 256 + threadIdx.x;
    if (i < n4) {
        float4 v = ((const float4*)in)[i];
        v.x = rtf(v.x); v.y = rtf(v.y); v.z = rtf(v.z); v.w = rtf(v.w);
        ((float4*)out)[i] = v;
    }
}

// ---------------- LayerNorm (tf32-rounded output; feeds only GEMM A) ----------------
__global__ __launch_bounds__(256) void ln_kernel(
    const float* __restrict__ x, const float* __restrict__ g,
    const float* __restrict__ b, float* __restrict__ y)
{
    int row = blockIdx.x;
    int t = threadIdx.x;
    const float4* xr = (const float4*)(x + (size_t)row * DM);
    float4 v = xr[t];
    float s  = v.x + v.y + v.z + v.w;
    float ss = v.x*v.x + v.y*v.y + v.z*v.z + v.w*v.w;
    #pragma unroll
    for (int o = 16; o > 0; o >>= 1) {
        s  += __shfl_xor_sync(0xffffffffu, s,  o);
        ss += __shfl_xor_sync(0xffffffffu, ss, o);
    }
    __shared__ float red[18];
    if ((t & 31) == 0) { red[t >> 5] = s; red[(t >> 5) + 8] = ss; }
    __syncthreads();
    if (t == 0) {
        float S_ = 0.f, SS = 0.f;
        #pragma unroll
        for (int i = 0; i < 8; i++) { S_ += red[i]; SS += red[i + 8]; }
        float mu  = S_ * (1.f / DM);
        float var = SS * (1.f / DM) - mu * mu;
        red[16] = mu;
        red[17] = rsqrtf(var + 1e-5f);
    }
    __syncthreads();
    float mu = red[16], inv = red[17];
    float4 gg = ((const float4*)g)[t];
    float4 bb = ((const float4*)b)[t];
    float4 o;
    o.x = rtf((v.x - mu) * inv * gg.x + bb.x);
    o.y = rtf((v.y - mu) * inv * gg.y + bb.y);
    o.z = rtf((v.z - mu) * inv * gg.z + bb.z);
    o.w = rtf((v.w - mu) * inv * gg.w + bb.w);
    ((float4*)(y + (size_t)row * DM))[t] = o;
}

// ---------------- tf32 TC GEMM (R3 shape, cvt-free): C[M,N]=A[M,K]@W[N,K]^T ----------------
// 128x128 block, BK=16, 256 threads = 8 warps (2m x 4n), warp tile 64x32,
// 2-stage cp.async, stride-20 smem. A and W MUST be tf32-pre-rounded.
#define CPA16(dst, src) \
    asm volatile("cp.async.cg.shared.global [%0], [%1], 16;\n" :: "r"(dst), "l"(src))

template<bool RELU, bool RES, bool ROUND>
__global__ __launch_bounds__(256) void gemm_tc(
    const float* __restrict__ A, const float* __restrict__ W,
    const float* __restrict__ bias, const float* __restrict__ res,
    float* __restrict__ C, int M, int N, int K)
{
    const int LDS_ = 20;
    __shared__ float As[2][128 * 20];
    __shared__ float Bs[2][128 * 20];
    int tid = threadIdx.x;
    int warp = tid >> 5, lane = tid & 31;
    int wm = warp >> 2, wn = warp & 3;
    int grp = lane >> 2, tig = lane & 3;
    int m0 = blockIdx.y << 7, n0 = blockIdx.x << 7;

    // loaders: rows lrow & lrow+64, cols lcol..lcol+3 (covers 128x16)
    int lrow = tid >> 2;
    int lcol = (tid & 3) << 2;
    const float* Ag = A + (size_t)(m0 + lrow) * K + lcol;
    const float* Wg = W + (size_t)(n0 + lrow) * K + lcol;
    uint32_t sA = (uint32_t)__cvta_generic_to_shared(&As[0][0]);
    uint32_t sB = (uint32_t)__cvta_generic_to_shared(&Bs[0][0]);
    uint32_t doff = (uint32_t)(lrow * LDS_ + lcol) * 4u;
    const uint32_t stageB = 128u * LDS_ * 4u;
    const uint32_t halfB  = 64u * LDS_ * 4u;

    float acc[4][4][4];
    #pragma unroll
    for (int mt = 0; mt < 4; mt++)
        #pragma unroll
        for (int nt = 0; nt < 4; nt++)
            #pragma unroll
            for (int i = 0; i < 4; i++) acc[mt][nt][i] = 0.f;

    int KT = K >> 4;
    {
        uint32_t ad = sA + doff, bd = sB + doff;
        CPA16(ad, Ag);
        CPA16(ad + halfB, Ag + (size_t)64 * K);
        CPA16(bd, Wg);
        CPA16(bd + halfB, Wg + (size_t)64 * K);
        asm volatile("cp.async.commit_group;\n");
    }

    for (int kt = 0; kt < KT; kt++) {
        if (kt + 1 < KT) {
            int k0 = (kt + 1) << 4;
            uint32_t st = ((kt + 1) & 1) * stageB;
            uint32_t ad = sA + st + doff, bd = sB + st + doff;
            CPA16(ad, Ag + k0);
            CPA16(ad + halfB, Ag + (size_t)64 * K + k0);
            CPA16(bd, Wg + k0);
            CPA16(bd + halfB, Wg + (size_t)64 * K + k0);
            asm volatile("cp.async.commit_group;\n");
            asm volatile("cp.async.wait_group 1;\n");
        } else {
            asm volatile("cp.async.wait_group 0;\n");
        }
        __syncthreads();

        const float* Asb = As[kt & 1];
        const float* Bsb = Bs[kt & 1];
        #pragma unroll
        for (int kk = 0; kk < 16; kk += 8) {
            uint32_t a[4][4], b[4][2];
            #pragma unroll
            for (int mt = 0; mt < 4; mt++) {
                int rb = wm * 64 + mt * 16;
                a[mt][0] = __float_as_uint(Asb[(rb + grp)     * LDS_ + kk + tig]);
                a[mt][1] = __float_as_uint(Asb[(rb + grp + 8) * LDS_ + kk + tig]);
                a[mt][2] = __float_as_uint(Asb[(rb + grp)     * LDS_ + kk + tig + 4]);
                a[mt][3] = __float_as_uint(Asb[(rb + grp + 8) * LDS_ + kk + tig + 4]);
            }
            #pragma unroll
            for (int nt = 0; nt < 4; nt++) {
                int cb = wn * 32 + nt * 8;
                b[nt][0] = __float_as_uint(Bsb[(cb + grp) * LDS_ + kk + tig]);
                b[nt][1] = __float_as_uint(Bsb[(cb + grp) * LDS_ + kk + tig + 4]);
            }
            #pragma unroll
            for (int mt = 0; mt < 4; mt++)
                #pragma unroll
                for (int nt = 0; nt < 4; nt++) {
                    asm volatile(
                        "mma.sync.aligned.m16n8k8.row.col.f32.tf32.tf32.f32 "
                        "{%0,%1,%2,%3}, {%4,%5,%6,%7}, {%8,%9}, {%0,%1,%2,%3};\n"
                        : "+f"(acc[mt][nt][0]), "+f"(acc[mt][nt][1]),
                          "+f"(acc[mt][nt][2]), "+f"(acc[mt][nt][3])
                        : "r"(a[mt][0]), "r"(a[mt][1]), "r"(a[mt][2]), "r"(a[mt][3]),
                          "r"(b[nt][0]), "r"(b[nt][1]));
                }
        }
        __syncthreads();
    }

    #pragma unroll
    for (int mt = 0; mt < 4; mt++) {
        int r = m0 + wm * 64 + mt * 16 + grp;
        #pragma unroll
        for (int nt = 0; nt < 4; nt++) {
            int c = n0 + wn * 32 + nt * 8 + tig * 2;
            float2 bv = *(const float2*)(bias + c);
            #pragma unroll
            for (int half = 0; half < 2; half++) {
                int rr = r + half * 8;
                float2 o;
                o.x = acc[mt][nt][half * 2 + 0] + bv.x;
                o.y = acc[mt][nt][half * 2 + 1] + bv.y;
                if (RES) {
                    float2 rv = *(const float2*)(res + (size_t)rr * N + c);
                    o.x += rv.x; o.y += rv.y;
                }
                if (RELU) { o.x = fmaxf(o.x, 0.f); o.y = fmaxf(o.y, 0.f); }
                if (ROUND) { o.x = rtf(o.x); o.y = rtf(o.y); }
                *(float2*)(C + (size_t)rr * N + c) = o;
            }
        }
    }
}

// ---------------- RoPE: outputs tf32-rounded, Q pre-scaled by 1/8 ----------------
__global__ __launch_bounds__(256) void rope_kernel(
    const float* __restrict__ qkv, const float* __restrict__ sn,
    const float* __restrict__ cs,
    float* __restrict__ Q, float* __restrict__ K, float* __restrict__ V)
{
    int idx = blockIdx.x * 256 + threadIdx.x;
    int p = idx & 31;
    int s = (idx >> 5) & 2047;
    int h = (idx >> 16) & 15;
    int b = idx >> 20;
    size_t rb = ((size_t)s * BAT + b) * (3 * DM) + h * HDM + 2 * p;
    float2 q = *(const float2*)(qkv + rb);
    float2 k = *(const float2*)(qkv + rb + DM);
    float2 v = *(const float2*)(qkv + rb + 2 * DM);
    float sv = sn[s * 32 + p], cv = cs[s * 32 + p];
    float2 qo = make_float2(rtf((q.x * cv - q.y * sv) * 0.125f),
                            rtf((q.y * cv + q.x * sv) * 0.125f));
    float2 ko = make_float2(rtf(k.x * cv - k.y * sv), rtf(k.y * cv + k.x * sv));
    float2 vo = make_float2(rtf(v.x), rtf(v.y));
    size_t ob = ((size_t)(b * NH + h) * SEQ + s) * HDM + 2 * p;
    *(float2*)(Q + ob) = qo;
    *(float2*)(K + ob) = ko;
    *(float2*)(V + ob) = vo;
}

// ---------------- tf32 TC flash attention (inputs pre-rounded) ----------------
#define KS_LD 68
#define VS_LD 72

__global__ __launch_bounds__(128) void attn_tc(
    const float* __restrict__ Q, const float* __restrict__ K,
    const float* __restrict__ V, float* __restrict__ Out)
{
    extern __shared__ float sm[];
    float* Ks = sm;                     // 64 x 68
    float* Vs = sm + 64 * KS_LD;        // 64 x 72
    float* Ps = Vs + 64 * VS_LD;        // 64 x 68 (Q staging, then P)
    int tid = threadIdx.x;
    int warp = tid >> 5, lane = tid & 31;
    int grp = lane >> 2, tig = lane & 3;
    int qb = blockIdx.x, bh = blockIdx.y;
    int b = bh >> 4, h = bh & 15;
    int rb = warp * 16;

    const float* Qg = Q + ((size_t)bh * SEQ + qb * 64) * HDM;
    #pragma unroll
    for (int i = 0; i < 8; i++) {
        int idx = tid + i * 128;
        int r = idx >> 4, c = (idx & 15) << 2;
        float4 v = *(const float4*)(Qg + r * 64 + c);
        Ps[r * KS_LD + c + 0] = v.x;
        Ps[r * KS_LD + c + 1] = v.y;
        Ps[r * KS_LD + c + 2] = v.z;
        Ps[r * KS_LD + c + 3] = v.w;
    }
    __syncthreads();

    uint32_t qa[8][4];
    #pragma unroll
    for (int kk = 0; kk < 8; kk++) {
        qa[kk][0] = __float_as_uint(Ps[(rb + grp)     * KS_LD + kk * 8 + tig]);
        qa[kk][1] = __float_as_uint(Ps[(rb + grp + 8) * KS_LD + kk * 8 + tig]);
        qa[kk][2] = __float_as_uint(Ps[(rb + grp)     * KS_LD + kk * 8 + tig + 4]);
        qa[kk][3] = __float_as_uint(Ps[(rb + grp + 8) * KS_LD + kk * 8 + tig + 4]);
    }

    float oacc[8][4];
    #pragma unroll
    for (int nt = 0; nt < 8; nt++)
        #pragma unroll
        for (int i = 0; i < 4; i++) oacc[nt][i] = 0.f;
    float m_i[2] = {-1e30f, -1e30f};
    float l_i[2] = {0.f, 0.f};

    for (int kb = 0; kb <= qb; kb++) {
        __syncthreads();
        const float* Kg = K + ((size_t)bh * SEQ + kb * 64) * HDM;
        const float* Vg = V + ((size_t)bh * SEQ + kb * 64) * HDM;
        #pragma unroll
        for (int i = 0; i < 8; i++) {
            int idx = tid + i * 128;
            int r = idx >> 4, c = (idx & 15) << 2;
            float4 kv = *(const float4*)(Kg + r * 64 + c);
            Ks[r * KS_LD + c + 0] = kv.x;
            Ks[r * KS_LD + c + 1] = kv.y;
            Ks[r * KS_LD + c + 2] = kv.z;
            Ks[r * KS_LD + c + 3] = kv.w;
            float4 vv = *(const float4*)(Vg + r * 64 + c);
            Vs[r * VS_LD + c + 0] = vv.x;
            Vs[r * VS_LD + c + 1] = vv.y;
            Vs[r * VS_LD + c + 2] = vv.z;
            Vs[r * VS_LD + c + 3] = vv.w;
        }
        __syncthreads();

        float sacc[8][4];
        #pragma unroll
        for (int nt = 0; nt < 8; nt++)
            #pragma unroll
            for (int i = 0; i < 4; i++) sacc[nt][i] = 0.f;
        #pragma unroll
        for (int kk = 0; kk < 8; kk++) {
            #pragma unroll
            for (int nt = 0; nt < 8; nt++) {
                uint32_t b0 = __float_as_uint(Ks[(nt * 8 + grp) * KS_LD + kk * 8 + tig]);
                uint32_t b1 = __float_as_uint(Ks[(nt * 8 + grp) * KS_LD + kk * 8 + tig + 4]);
                asm volatile(
                    "mma.sync.aligned.m16n8k8.row.col.f32.tf32.tf32.f32 "
                    "{%0,%1,%2,%3}, {%4,%5,%6,%7}, {%8,%9}, {%0,%1,%2,%3};\n"
                    : "+f"(sacc[nt][0]), "+f"(sacc[nt][1]),
                      "+f"(sacc[nt][2]), "+f"(sacc[nt][3])
                    : "r"(qa[kk][0]), "r"(qa[kk][1]), "r"(qa[kk][2]), "r"(qa[kk][3]),
                      "r"(b0), "r"(b1));
            }
        }

        if (kb == qb) {
            #pragma unroll
            for (int nt = 0; nt < 8; nt++) {
                int c0 = nt * 8 + 2 * tig;
                int r0 = rb + grp;
                if (c0     > r0)     sacc[nt][0] = -1e30f;
                if (c0 + 1 > r0)     sacc[nt][1] = -1e30f;
                if (c0     > r0 + 8) sacc[nt][2] = -1e30f;
                if (c0 + 1 > r0 + 8) sacc[nt][3] = -1e30f;
            }
        }

        #pragma unroll
        for (int hf = 0; hf < 2; hf++) {
            float mx = -1e30f;
            #pragma unroll
            for (int nt = 0; nt < 8; nt++)
                mx = fmaxf(mx, fmaxf(sacc[nt][2 * hf], sacc[nt][2 * hf + 1]));
            mx = fmaxf(mx, __shfl_xor_sync(0xffffffffu, mx, 1));
            mx = fmaxf(mx, __shfl_xor_sync(0xffffffffu, mx, 2));
            float mn = fmaxf(m_i[hf], mx);
            float al = __expf(m_i[hf] - mn);
            float rs = 0.f;
            int prow = (rb + grp + 8 * hf) * KS_LD;
            #pragma unroll
            for (int nt = 0; nt < 8; nt++) {
                float p0 = __expf(sacc[nt][2 * hf]     - mn);
                float p1 = __expf(sacc[nt][2 * hf + 1] - mn);
                rs += p0 + p1;
                float2 st;
                st.x = __uint_as_float(f2tf32(p0));
                st.y = __uint_as_float(f2tf32(p1));
                *(float2*)(Ps + prow + nt * 8 + 2 * tig) = st;
                oacc[nt][2 * hf]     *= al;
                oacc[nt][2 * hf + 1] *= al;
            }
            rs += __shfl_xor_sync(0xffffffffu, rs, 1);
            rs += __shfl_xor_sync(0xffffffffu, rs, 2);
            l_i[hf] = l_i[hf] * al + rs;
            m_i[hf] = mn;
        }
        __syncwarp();

        #pragma unroll
        for (int kk = 0; kk < 8; kk++) {
            uint32_t a0 = __float_as_uint(Ps[(rb + grp)     * KS_LD + kk * 8 + tig]);
            uint32_t a1 = __float_as_uint(Ps[(rb + grp + 8) * KS_LD + kk * 8 + tig]);
            uint32_t a2 = __float_as_uint(Ps[(rb + grp)     * KS_LD + kk * 8 + tig + 4]);
            uint32_t a3 = __float_as_uint(Ps[(rb + grp + 8) * KS_LD + kk * 8 + tig + 4]);
            #pragma unroll
            for (int nt = 0; nt < 8; nt++) {
                uint32_t b0 = __float_as_uint(Vs[(kk * 8 + tig)     * VS_LD + nt * 8 + grp]);
                uint32_t b1 = __float_as_uint(Vs[(kk * 8 + tig + 4) * VS_LD + nt * 8 + grp]);
                asm volatile(
                    "mma.sync.aligned.m16n8k8.row.col.f32.tf32.tf32.f32 "
                    "{%0,%1,%2,%3}, {%4,%5,%6,%7}, {%8,%9}, {%0,%1,%2,%3};\n"
                    : "+f"(oacc[nt][0]), "+f"(oacc[nt][1]),
                      "+f"(oacc[nt][2]), "+f"(oacc[nt][3])
                    : "r"(a0), "r"(a1), "r"(a2), "r"(a3),
                      "r"(b0), "r"(b1));
            }
        }
    }

    float inv0 = 1.f / l_i[0], inv1 = 1.f / l_i[1];
    int q0 = qb * 64 + rb + grp;
    #pragma unroll
    for (int nt = 0; nt < 8; nt++) {
        int d = h * HDM + nt * 8 + 2 * tig;
        float2 o0 = make_float2(rtf(oacc[nt][0] * inv0), rtf(oacc[nt][1] * inv0));
        float2 o1 = make_float2(rtf(oacc[nt][2] * inv1), rtf(oacc[nt][3] * inv1));
        *(float2*)(Out + ((size_t)q0 * BAT + b) * DM + d)       = o0;
        *(float2*)(Out + ((size_t)(q0 + 8) * BAT + b) * DM + d) = o1;
    }
}

// ---------------- launcher ----------------
extern "C" void kernel_launch(void* const* d_in, const int* in_sizes, int n_in,
                              void* d_out, int out_size)
{
    const float* src  = (const float*)d_in[0];
    const float* sn   = (const float*)d_in[1];
    const float* cs   = (const float*)d_in[2];
    const float* wqkv = (const float*)d_in[3];
    const float* bqkv = (const float*)d_in[4];
    const float* wo   = (const float*)d_in[5];
    const float* bo   = (const float*)d_in[6];
    const float* g1   = (const float*)d_in[7];
    const float* be1  = (const float*)d_in[8];
    const float* g2   = (const float*)d_in[9];
    const float* be2  = (const float*)d_in[10];
    const float* w1   = (const float*)d_in[11];
    const float* bb1  = (const float*)d_in[12];
    const float* w2   = (const float*)d_in[13];
    const float* bb2  = (const float*)d_in[14];
    float* out = (float*)d_out;

    float *xln, *qkv, *q, *k, *v, *att, *x, *h1;
    float *rwqkv, *rwo, *rw1, *rw2;
    cudaGetSymbolAddress((void**)&xln, g_xln);
    cudaGetSymbolAddress((void**)&qkv, g_qkv);
    cudaGetSymbolAddress((void**)&q,   g_q);
    cudaGetSymbolAddress((void**)&k,   g_k);
    cudaGetSymbolAddress((void**)&v,   g_v);
    cudaGetSymbolAddress((void**)&att, g_att);
    cudaGetSymbolAddress((void**)&x,   g_x);
    cudaGetSymbolAddress((void**)&h1,  g_h1);
    cudaGetSymbolAddress((void**)&rwqkv, g_wqkv);
    cudaGetSymbolAddress((void**)&rwo,   g_wo);
    cudaGetSymbolAddress((void**)&rw1,   g_w1);
    cudaGetSymbolAddress((void**)&rw2,   g_w2);

    const int ATTN_SMEM = (64 * KS_LD + 64 * VS_LD + 64 * KS_LD) * 4;
    cudaFuncSetAttribute(attn_tc, cudaFuncAttributeMaxDynamicSharedMemorySize, ATTN_SMEM);

    // 0. pre-round weights to tf32
    round_kernel<<<(3 * DM * DM / 4 + 255) / 256, 256>>>(wqkv, rwqkv, 3 * DM * DM / 4);
    round_kernel<<<(DM * DM / 4 + 255) / 256, 256>>>(wo, rwo, DM * DM / 4);
    round_kernel<<<(DFF * DM / 4 + 255) / 256, 256>>>(w1, rw1, DFF * DM / 4);
    round_kernel<<<(DM * DFF / 4 + 255) / 256, 256>>>(w2, rw2, DM * DFF / 4);

    // 1. LN1 (tf32 out)
    ln_kernel<<<ROWS, 256>>>(src, g1, be1, xln);
    // 2. QKV projection
    gemm_tc<false, false, false><<<dim3(3 * DM / 128, ROWS / 128), 256>>>(
        xln, rwqkv, bqkv, nullptr, qkv, ROWS, 3 * DM, DM);
    // 3. RoPE (tf32 out, Q pre-scaled)
    rope_kernel<<<(BAT * NH * SEQ * 32) / 256, 256>>>(qkv, sn, cs, q, k, v);
    // 4. attention (tf32 out)
    attn_tc<<<dim3(SEQ / 64, BAT * NH), 128, ATTN_SMEM>>>(q, k, v, att);
    // 5. out-proj + residual (fp32 out)
    gemm_tc<false, true, false><<<dim3(DM / 128, ROWS / 128), 256>>>(
        att, rwo, bo, src, x, ROWS, DM, DM);
    // 6. LN2 (tf32 out)
    ln_kernel<<<ROWS, 256>>>(x, g2, be2, xln);
    // 7. FFN up + ReLU (tf32 out)
    gemm_tc<true, false, true><<<dim3(DFF / 128, ROWS / 128), 256>>>(
        xln, rw1, bb1, nullptr, h1, ROWS, DFF, DM);
    // 8. FFN down + residual (fp32 out)
    gemm_tc<false, true, false><<<dim3(DM / 128, ROWS / 128), 256>>>(
        h1, rw2, bb2, x, out, ROWS, DM, DFF);
}

// round 9
// speedup vs baseline: 2.0150x; 1.6947x over previous
#include <cuda_runtime.h>
#include <cuda_fp16.h>
#include <math.h>
#include <stdint.h>

#define SEQ  2048
#define BAT  2
#define DM   1024
#define NH   16
#define HDM  64
#define DFF  4096
#define ROWS (SEQ*BAT)   // 4096

// ---------------- scratch (static device globals; no allocation) ----------------
__device__ __half g_xln[ROWS * DM];
__device__ __half g_qkv[ROWS * 3 * DM];
__device__ __half g_q[BAT * NH * SEQ * HDM];
__device__ __half g_k[BAT * NH * SEQ * HDM];
__device__ __half g_v[BAT * NH * SEQ * HDM];
__device__ __half g_vt[BAT * NH * SEQ * HDM];   // V transposed [bh][d][s]
__device__ __half g_att[ROWS * DM];
__device__ float  g_x[ROWS * DM];
__device__ __half g_h1[ROWS * DFF];
__device__ __half g_wqkv[3 * DM * DM];
__device__ __half g_wo[DM * DM];
__device__ __half g_w1[DFF * DM];
__device__ __half g_w2[DM * DFF];

#define CPA16(dst, src) \
    asm volatile("cp.async.cg.shared.global [%0], [%1], 16;\n" :: "r"(dst), "l"(src))

#define MMA16816(d, a0, a1, a2, a3, b0, b1) \
    asm volatile("mma.sync.aligned.m16n8k16.row.col.f32.f16.f16.f32 " \
        "{%0,%1,%2,%3}, {%4,%5,%6,%7}, {%8,%9}, {%0,%1,%2,%3};\n" \
        : "+f"((d)[0]), "+f"((d)[1]), "+f"((d)[2]), "+f"((d)[3]) \
        : "r"(a0), "r"(a1), "r"(a2), "r"(a3), "r"(b0), "r"(b1))

// ---------------- fp32 -> fp16 weight convert ----------------
__global__ __launch_bounds__(256) void cvt_kernel(
    const float* __restrict__ in, __half* __restrict__ out, int n4)
{
    int i = blockIdx.x * 256 + threadIdx.x;
    if (i < n4) {
        float4 v = ((const float4*)in)[i];
        __half2* o = (__half2*)(out + (size_t)i * 4);
        o[0] = __floats2half2_rn(v.x, v.y);
        o[1] = __floats2half2_rn(v.z, v.w);
    }
}

// ---------------- LayerNorm (fp32 in, fp16 out) ----------------
__global__ __launch_bounds__(256) void ln_kernel(
    const float* __restrict__ x, const float* __restrict__ g,
    const float* __restrict__ b, __half* __restrict__ y)
{
    int row = blockIdx.x;
    int t = threadIdx.x;
    const float4* xr = (const float4*)(x + (size_t)row * DM);
    float4 v = xr[t];
    float s  = v.x + v.y + v.z + v.w;
    float ss = v.x*v.x + v.y*v.y + v.z*v.z + v.w*v.w;
    #pragma unroll
    for (int o = 16; o > 0; o >>= 1) {
        s  += __shfl_xor_sync(0xffffffffu, s,  o);
        ss += __shfl_xor_sync(0xffffffffu, ss, o);
    }
    __shared__ float red[18];
    if ((t & 31) == 0) { red[t >> 5] = s; red[(t >> 5) + 8] = ss; }
    __syncthreads();
    if (t == 0) {
        float S_ = 0.f, SS = 0.f;
        #pragma unroll
        for (int i = 0; i < 8; i++) { S_ += red[i]; SS += red[i + 8]; }
        float mu  = S_ * (1.f / DM);
        float var = SS * (1.f / DM) - mu * mu;
        red[16] = mu;
        red[17] = rsqrtf(var + 1e-5f);
    }
    __syncthreads();
    float mu = red[16], inv = red[17];
    float4 gg = ((const float4*)g)[t];
    float4 bb = ((const float4*)b)[t];
    __half2* yr = (__half2*)(y + (size_t)row * DM) + t * 2;
    yr[0] = __floats2half2_rn((v.x - mu) * inv * gg.x + bb.x,
                              (v.y - mu) * inv * gg.y + bb.y);
    yr[1] = __floats2half2_rn((v.z - mu) * inv * gg.z + bb.z,
                              (v.w - mu) * inv * gg.w + bb.w);
}

// ---------------- fp16 TC GEMM: C[M,N] = A[M,K] @ W[N,K]^T ----------------
// 128x128 block, BK=32 halfs, 256 threads = 8 warps (2m x 4n), warp tile 64x32,
// m16n8k16 f16 mma, 2-stage cp.async, stride-40-half smem (conflict-free).
template<bool RELU, bool RES, bool OUTH>
__global__ __launch_bounds__(256) void gemm_h(
    const __half* __restrict__ A, const __half* __restrict__ W,
    const float* __restrict__ bias, const float* __restrict__ res,
    void* __restrict__ Cv, int M, int N, int K)
{
    const int LDH = 40;   // halfs per smem row (20 b32)
    __shared__ __half As[2][128 * 40];
    __shared__ __half Bs[2][128 * 40];
    int tid = threadIdx.x;
    int warp = tid >> 5, lane = tid & 31;
    int wm = warp >> 2, wn = warp & 3;
    int grp = lane >> 2, tig = lane & 3;
    int m0 = blockIdx.y << 7, n0 = blockIdx.x << 7;

    int lrow = tid >> 1;            // 0..127
    int lcol = (tid & 1) << 4;      // 0 or 16 halfs
    const __half* Ag = A + (size_t)(m0 + lrow) * K + lcol;
    const __half* Wg = W + (size_t)(n0 + lrow) * K + lcol;
    uint32_t sA = (uint32_t)__cvta_generic_to_shared(&As[0][0]);
    uint32_t sB = (uint32_t)__cvta_generic_to_shared(&Bs[0][0]);
    uint32_t doff = (uint32_t)(lrow * LDH + lcol) * 2u;
    const uint32_t stageB = 128u * LDH * 2u;   // 10240

    float acc[4][4][4];
    #pragma unroll
    for (int mt = 0; mt < 4; mt++)
        #pragma unroll
        for (int nt = 0; nt < 4; nt++)
            #pragma unroll
            for (int i = 0; i < 4; i++) acc[mt][nt][i] = 0.f;

    int KT = K >> 5;
    {
        CPA16(sA + doff,      Ag);
        CPA16(sA + doff + 16, Ag + 8);
        CPA16(sB + doff,      Wg);
        CPA16(sB + doff + 16, Wg + 8);
        asm volatile("cp.async.commit_group;\n");
    }

    for (int kt = 0; kt < KT; kt++) {
        if (kt + 1 < KT) {
            int k0 = (kt + 1) << 5;
            uint32_t st = ((kt + 1) & 1) * stageB;
            CPA16(sA + st + doff,      Ag + k0);
            CPA16(sA + st + doff + 16, Ag + k0 + 8);
            CPA16(sB + st + doff,      Wg + k0);
            CPA16(sB + st + doff + 16, Wg + k0 + 8);
            asm volatile("cp.async.commit_group;\n");
            asm volatile("cp.async.wait_group 1;\n");
        } else {
            asm volatile("cp.async.wait_group 0;\n");
        }
        __syncthreads();

        const uint32_t* Asb = (const uint32_t*)As[kt & 1];
        const uint32_t* Bsb = (const uint32_t*)Bs[kt & 1];
        #pragma unroll
        for (int kk2 = 0; kk2 < 2; kk2++) {
            uint32_t a[4][4], b[4][2];
            int kof = kk2 * 8 + tig;
            #pragma unroll
            for (int mt = 0; mt < 4; mt++) {
                int rb = wm * 64 + mt * 16;
                a[mt][0] = Asb[(rb + grp)     * 20 + kof];
                a[mt][1] = Asb[(rb + grp + 8) * 20 + kof];
                a[mt][2] = Asb[(rb + grp)     * 20 + kof + 4];
                a[mt][3] = Asb[(rb + grp + 8) * 20 + kof + 4];
            }
            #pragma unroll
            for (int nt = 0; nt < 4; nt++) {
                int cb = wn * 32 + nt * 8;
                b[nt][0] = Bsb[(cb + grp) * 20 + kof];
                b[nt][1] = Bsb[(cb + grp) * 20 + kof + 4];
            }
            #pragma unroll
            for (int mt = 0; mt < 4; mt++)
                #pragma unroll
                for (int nt = 0; nt < 4; nt++)
                    MMA16816(acc[mt][nt], a[mt][0], a[mt][1], a[mt][2], a[mt][3],
                             b[nt][0], b[nt][1]);
        }
        __syncthreads();
    }

    #pragma unroll
    for (int mt = 0; mt < 4; mt++) {
        int r = m0 + wm * 64 + mt * 16 + grp;
        #pragma unroll
        for (int nt = 0; nt < 4; nt++) {
            int c = n0 + wn * 32 + nt * 8 + tig * 2;
            float2 bv = *(const float2*)(bias + c);
            #pragma unroll
            for (int half = 0; half < 2; half++) {
                int rr = r + half * 8;
                float ox = acc[mt][nt][half * 2 + 0] + bv.x;
                float oy = acc[mt][nt][half * 2 + 1] + bv.y;
                if (RES) {
                    float2 rv = *(const float2*)(res + (size_t)rr * N + c);
                    ox += rv.x; oy += rv.y;
                }
                if (RELU) { ox = fmaxf(ox, 0.f); oy = fmaxf(oy, 0.f); }
                if (OUTH) {
                    *(__half2*)((__half*)Cv + (size_t)rr * N + c) =
                        __floats2half2_rn(ox, oy);
                } else {
                    *(float2*)((float*)Cv + (size_t)rr * N + c) =
                        make_float2(ox, oy);
                }
            }
        }
    }
}

// ---------------- RoPE (fp16 in/out, Q pre-scaled by 1/8) ----------------
__global__ __launch_bounds__(256) void rope_kernel(
    const __half* __restrict__ qkv, const float* __restrict__ sn,
    const float* __restrict__ cs,
    __half* __restrict__ Q, __half* __restrict__ K, __half* __restrict__ V)
{
    int idx = blockIdx.x * 256 + threadIdx.x;
    int p = idx & 31;
    int s = (idx >> 5) & 2047;
    int h = (idx >> 16) & 15;
    int b = idx >> 20;
    size_t rb = ((size_t)s * BAT + b) * (3 * DM) + h * HDM + 2 * p;
    float2 q = __half22float2(*(const __half2*)(qkv + rb));
    float2 k = __half22float2(*(const __half2*)(qkv + rb + DM));
    float2 v = __half22float2(*(const __half2*)(qkv + rb + 2 * DM));
    float sv = sn[s * 32 + p], cv = cs[s * 32 + p];
    size_t ob = ((size_t)(b * NH + h) * SEQ + s) * HDM + 2 * p;
    *(__half2*)(Q + ob) = __floats2half2_rn((q.x * cv - q.y * sv) * 0.125f,
                                            (q.y * cv + q.x * sv) * 0.125f);
    *(__half2*)(K + ob) = __floats2half2_rn(k.x * cv - k.y * sv,
                                            k.y * cv + k.x * sv);
    *(__half2*)(V + ob) = __floats2half2_rn(v.x, v.y);
}

// ---------------- V transpose: [bh][s][d] -> [bh][d][s] ----------------
__global__ __launch_bounds__(256) void vt_kernel(
    const __half* __restrict__ V, __half* __restrict__ Vt)
{
    __shared__ __half t[64][72];
    int tid = threadIdx.x;
    int bh = blockIdx.y, s0 = blockIdx.x * 64;
    #pragma unroll
    for (int i = 0; i < 2; i++) {
        int lin = tid + i * 256;
        int r = lin >> 3, c8 = (lin & 7) * 8;   // r = s row, c8 = d chunk
        uint4 v = *(const uint4*)(V + ((size_t)bh * SEQ + s0 + r) * 64 + c8);
        const __half* hv = (const __half*)&v;
        #pragma unroll
        for (int j = 0; j < 8; j++) t[c8 + j][r] = hv[j];
    }
    __syncthreads();
    #pragma unroll
    for (int i = 0; i < 2; i++) {
        int lin = tid + i * 256;
        int r = lin >> 3, c8 = (lin & 7) * 8;   // r = d row, c8 = s chunk
        uint4 o = *(const uint4*)&t[r][c8];
        *(uint4*)(Vt + ((size_t)bh * 64 + r) * SEQ + s0 + c8) = o;
    }
}

// ---------------- fp16 TC flash attention ----------------
// 64-q tiles, 128 threads = 4 warps x 16 rows; smem rows stride 72 halfs (36 b32).
#define AT_LD 72
#define ATTN_SMEM (3 * 64 * AT_LD * 2)   // 27648 bytes

__global__ __launch_bounds__(128) void attn_h(
    const __half* __restrict__ Q, const __half* __restrict__ K,
    const __half* __restrict__ Vt, __half* __restrict__ Out)
{
    extern __shared__ __half smh[];
    __half* Ks = smh;                    // 64 x 72 (K tile, [key][d])
    __half* Vs = smh + 64 * AT_LD;       // 64 x 72 (Vt tile, [d][key])
    __half* Ps = smh + 2 * 64 * AT_LD;   // 64 x 72 (Q staging, then P [q][key])
    int tid = threadIdx.x;
    int warp = tid >> 5, lane = tid & 31;
    int grp = lane >> 2, tig = lane & 3;
    int qb = blockIdx.x, bh = blockIdx.y;
    int b = bh >> 4, h = bh & 15;
    int rb = warp * 16;

    const __half* Qg = Q + ((size_t)bh * SEQ + qb * 64) * HDM;
    #pragma unroll
    for (int i = 0; i < 4; i++) {
        int lin = tid + i * 128;
        int r = lin >> 3, c8 = (lin & 7) * 8;
        *(uint4*)(Ps + r * AT_LD + c8) = *(const uint4*)(Qg + r * 64 + c8);
    }
    __syncthreads();

    uint32_t qa[4][4];
    {
        const uint32_t* Psw = (const uint32_t*)Ps;
        #pragma unroll
        for (int kk2 = 0; kk2 < 4; kk2++) {
            int kof = kk2 * 8 + tig;
            qa[kk2][0] = Psw[(rb + grp)     * 36 + kof];
            qa[kk2][1] = Psw[(rb + grp + 8) * 36 + kof];
            qa[kk2][2] = Psw[(rb + grp)     * 36 + kof + 4];
            qa[kk2][3] = Psw[(rb + grp + 8) * 36 + kof + 4];
        }
    }
    __syncwarp();

    float oacc[8][4];
    #pragma unroll
    for (int nt = 0; nt < 8; nt++)
        #pragma unroll
        for (int i = 0; i < 4; i++) oacc[nt][i] = 0.f;
    float m_i[2] = {-1e30f, -1e30f};
    float l_i[2] = {0.f, 0.f};

    for (int kb = 0; kb <= qb; kb++) {
        __syncthreads();   // prior PV reads of Ks/Vs done (Ps is warp-private)
        const __half* Kg = K  + ((size_t)bh * SEQ + kb * 64) * HDM;
        const __half* Vg = Vt + (size_t)bh * 64 * SEQ + kb * 64;
        #pragma unroll
        for (int i = 0; i < 4; i++) {
            int lin = tid + i * 128;
            int r = lin >> 3, c8 = (lin & 7) * 8;
            *(uint4*)(Ks + r * AT_LD + c8) = *(const uint4*)(Kg + r * 64 + c8);
            *(uint4*)(Vs + r * AT_LD + c8) = *(const uint4*)(Vg + (size_t)r * SEQ + c8);
        }
        __syncthreads();

        float sacc[8][4];
        #pragma unroll
        for (int nt = 0; nt < 8; nt++)
            #pragma unroll
            for (int i = 0; i < 4; i++) sacc[nt][i] = 0.f;
        {
            const uint32_t* Ksw = (const uint32_t*)Ks;
            #pragma unroll
            for (int kk2 = 0; kk2 < 4; kk2++) {
                int kof = kk2 * 8 + tig;
                #pragma unroll
                for (int nt = 0; nt < 8; nt++) {
                    uint32_t b0 = Ksw[(nt * 8 + grp) * 36 + kof];
                    uint32_t b1 = Ksw[(nt * 8 + grp) * 36 + kof + 4];
                    MMA16816(sacc[nt], qa[kk2][0], qa[kk2][1], qa[kk2][2], qa[kk2][3],
                             b0, b1);
                }
            }
        }

        if (kb == qb) {
            #pragma unroll
            for (int nt = 0; nt < 8; nt++) {
                int c0 = nt * 8 + 2 * tig;
                int r0 = rb + grp;
                if (c0     > r0)     sacc[nt][0] = -1e30f;
                if (c0 + 1 > r0)     sacc[nt][1] = -1e30f;
                if (c0     > r0 + 8) sacc[nt][2] = -1e30f;
                if (c0 + 1 > r0 + 8) sacc[nt][3] = -1e30f;
            }
        }

        #pragma unroll
        for (int hf = 0; hf < 2; hf++) {
            float mx = -1e30f;
            #pragma unroll
            for (int nt = 0; nt < 8; nt++)
                mx = fmaxf(mx, fmaxf(sacc[nt][2 * hf], sacc[nt][2 * hf + 1]));
            mx = fmaxf(mx, __shfl_xor_sync(0xffffffffu, mx, 1));
            mx = fmaxf(mx, __shfl_xor_sync(0xffffffffu, mx, 2));
            float mn = fmaxf(m_i[hf], mx);
            float al = __expf(m_i[hf] - mn);
            float rs = 0.f;
            __half2* Prow = (__half2*)(Ps + (rb + grp + 8 * hf) * AT_LD);
            #pragma unroll
            for (int nt = 0; nt < 8; nt++) {
                float p0 = __expf(sacc[nt][2 * hf]     - mn);
                float p1 = __expf(sacc[nt][2 * hf + 1] - mn);
                rs += p0 + p1;
                Prow[nt * 4 + tig] = __floats2half2_rn(p0, p1);
                oacc[nt][2 * hf]     *= al;
                oacc[nt][2 * hf + 1] *= al;
            }
            rs += __shfl_xor_sync(0xffffffffu, rs, 1);
            rs += __shfl_xor_sync(0xffffffffu, rs, 2);
            l_i[hf] = l_i[hf] * al + rs;
            m_i[hf] = mn;
        }
        __syncwarp();

        {
            const uint32_t* Psw = (const uint32_t*)Ps;
            const uint32_t* Vsw = (const uint32_t*)Vs;
            #pragma unroll
            for (int kk2 = 0; kk2 < 4; kk2++) {
                int kof = kk2 * 8 + tig;
                uint32_t a0 = Psw[(rb + grp)     * 36 + kof];
                uint32_t a1 = Psw[(rb + grp + 8) * 36 + kof];
                uint32_t a2 = Psw[(rb + grp)     * 36 + kof + 4];
                uint32_t a3 = Psw[(rb + grp + 8) * 36 + kof + 4];
                #pragma unroll
                for (int nt = 0; nt < 8; nt++) {
                    uint32_t b0 = Vsw[(nt * 8 + grp) * 36 + kof];
                    uint32_t b1 = Vsw[(nt * 8 + grp) * 36 + kof + 4];
                    MMA16816(oacc[nt], a0, a1, a2, a3, b0, b1);
                }
            }
        }
        __syncwarp();
    }

    float inv0 = 1.f / l_i[0], inv1 = 1.f / l_i[1];
    int q0 = qb * 64 + rb + grp;
    #pragma unroll
    for (int nt = 0; nt < 8; nt++) {
        int d = h * HDM + nt * 8 + 2 * tig;
        *(__half2*)(Out + ((size_t)q0 * BAT + b) * DM + d) =
            __floats2half2_rn(oacc[nt][0] * inv0, oacc[nt][1] * inv0);
        *(__half2*)(Out + ((size_t)(q0 + 8) * BAT + b) * DM + d) =
            __floats2half2_rn(oacc[nt][2] * inv1, oacc[nt][3] * inv1);
    }
}

// ---------------- launcher ----------------
extern "C" void kernel_launch(void* const* d_in, const int* in_sizes, int n_in,
                              void* d_out, int out_size)
{
    const float* src  = (const float*)d_in[0];
    const float* sn   = (const float*)d_in[1];
    const float* cs   = (const float*)d_in[2];
    const float* wqkv = (const float*)d_in[3];
    const float* bqkv = (const float*)d_in[4];
    const float* wo   = (const float*)d_in[5];
    const float* bo   = (const float*)d_in[6];
    const float* g1   = (const float*)d_in[7];
    const float* be1  = (const float*)d_in[8];
    const float* g2   = (const float*)d_in[9];
    const float* be2  = (const float*)d_in[10];
    const float* w1   = (const float*)d_in[11];
    const float* bb1  = (const float*)d_in[12];
    const float* w2   = (const float*)d_in[13];
    const float* bb2  = (const float*)d_in[14];
    float* out = (float*)d_out;

    __half *xln, *qkv, *q, *k, *v, *vt, *att, *h1;
    __half *hwqkv, *hwo, *hw1, *hw2;
    float *x;
    cudaGetSymbolAddress((void**)&xln, g_xln);
    cudaGetSymbolAddress((void**)&qkv, g_qkv);
    cudaGetSymbolAddress((void**)&q,   g_q);
    cudaGetSymbolAddress((void**)&k,   g_k);
    cudaGetSymbolAddress((void**)&v,   g_v);
    cudaGetSymbolAddress((void**)&vt,  g_vt);
    cudaGetSymbolAddress((void**)&att, g_att);
    cudaGetSymbolAddress((void**)&x,   g_x);
    cudaGetSymbolAddress((void**)&h1,  g_h1);
    cudaGetSymbolAddress((void**)&hwqkv, g_wqkv);
    cudaGetSymbolAddress((void**)&hwo,   g_wo);
    cudaGetSymbolAddress((void**)&hw1,   g_w1);
    cudaGetSymbolAddress((void**)&hw2,   g_w2);

    cudaFuncSetAttribute(attn_h, cudaFuncAttributeMaxDynamicSharedMemorySize, ATTN_SMEM);

    // 0. weights -> fp16
    cvt_kernel<<<(3 * DM * DM / 4 + 255) / 256, 256>>>(wqkv, hwqkv, 3 * DM * DM / 4);
    cvt_kernel<<<(DM * DM / 4 + 255) / 256, 256>>>(wo, hwo, DM * DM / 4);
    cvt_kernel<<<(DFF * DM / 4 + 255) / 256, 256>>>(w1, hw1, DFF * DM / 4);
    cvt_kernel<<<(DM * DFF / 4 + 255) / 256, 256>>>(w2, hw2, DM * DFF / 4);

    // 1. LN1 (fp16 out)
    ln_kernel<<<ROWS, 256>>>(src, g1, be1, xln);
    // 2. QKV projection (fp16 out)
    gemm_h<false, false, true><<<dim3(3 * DM / 128, ROWS / 128), 256>>>(
        xln, hwqkv, bqkv, nullptr, qkv, ROWS, 3 * DM, DM);
    // 3. RoPE (fp16, Q pre-scaled)
    rope_kernel<<<(BAT * NH * SEQ * 32) / 256, 256>>>(qkv, sn, cs, q, k, v);
    // 3b. V transpose [bh][s][d] -> [bh][d][s]
    vt_kernel<<<dim3(SEQ / 64, BAT * NH), 256>>>(v, vt);
    // 4. attention (fp16 out)
    attn_h<<<dim3(SEQ / 64, BAT * NH), 128, ATTN_SMEM>>>(q, k, vt, att);
    // 5. out-proj + residual (fp32 out)
    gemm_h<false, true, false><<<dim3(DM / 128, ROWS / 128), 256>>>(
        att, hwo, bo, src, x, ROWS, DM, DM);
    // 6. LN2 (fp16 out)
    ln_kernel<<<ROWS, 256>>>(x, g2, be2, xln);
    // 7. FFN up + ReLU (fp16 out)
    gemm_h<true, false, true><<<dim3(DFF / 128, ROWS / 128), 256>>>(
        xln, hw1, bb1, nullptr, h1, ROWS, DFF, DM);
    // 8. FFN down + residual (fp32 out) -> final output
    gemm_h<false, true, false><<<dim3(DM / 128, ROWS / 128), 256>>>(
        h1, hw2, bb2, x, out, ROWS, DM, DFF);
}